// round 10
// baseline (speedup 1.0000x reference)
#include <cuda_runtime.h>

#define HH 112
#define WW 112
#define CCH 64
#define BBATCH 32
#define BANDS 4
#define BH 28             // output rows per band
#define NSTEP 32          // BH + 4 halo rows
#define BX 32             // lanes; 0..27 own 4-col groups
#define NCG 28
#define NTHREADS 128

__device__ __forceinline__ float frcp(float d) {
    float r; asm("rcp.approx.f32 %0, %1;" : "=f"(r) : "f"(d)); return r;
}
__device__ __forceinline__ int iclamp(int v, int lo, int hi) {
    return v < lo ? lo : (v > hi ? hi : v);
}

__global__ __launch_bounds__(NTHREADS, 8)
void bionorm_kernel(const float* __restrict__ x,
                    const float* __restrict__ sigma,
                    const float* __restrict__ pow_p,
                    const float* __restrict__ sum_kernel,
                    const float* __restrict__ weight,
                    const float* __restrict__ bias,
                    float* __restrict__ out)
{
    __shared__ float kc_sh[25];
    __shared__ float sp_sh;
    __shared__ int   uni_sh;

    const int tx  = threadIdx.x;             // lane: column group (0..27 active)
    const int ty  = threadIdx.y;             // band 0..3
    const int tid = ty * BX + tx;
    const int c   = blockIdx.x;
    const int b   = blockIdx.y;
    const int r0  = ty * BH;
    const int w4  = 4 * tx;
    const bool act = (tx < NCG);
    const int wl4 = act ? w4 : WW - 4;       // safe col for idle lanes

    const float p  = pow_p[c];
    const bool  sq = (p == 2.0f);

    if (tid < 25) kc_sh[tid] = sum_kernel[c * 25 + tid];
    if (tid == 0) {
        float s = sigma[c];
        sp_sh = sq ? s * s : powf(s, p);
        const float* kp = sum_kernel + c * 25;
        float k0 = kp[0];
        int u = 1;
        #pragma unroll
        for (int i = 1; i < 25; i++) u &= (kp[i] == k0);
        uni_sh = u;
    }
    __syncthreads();

    const float* __restrict__ xin  = x   + (size_t)(b * CCH + c) * (HH * WW);
    float* __restrict__       oimg = out + (size_t)(b * CCH + c) * (HH * WW);
    const float sp  = sp_sh;
    const float wgt = weight[c];
    const float bs  = bias[c];

    if (uni_sh) {
        // ========== FAST PATH: register-streaming separable box filter =====
        const float k0 = kc_sh[0];

        float4 hist[5];                      // hsum history (circular 5)
        float4 s4  = make_float4(0.f, 0.f, 0.f, 0.f);   // running 5-row sum
        float4 sft = make_float4(0.f, 0.f, 0.f, 0.f);   // sf at center 109 (last band)
        #pragma unroll
        for (int q = 0; q < 5; q++) hist[q] = make_float4(0.f, 0.f, 0.f, 0.f);

        #pragma unroll
        for (int i = 0; i < NSTEP; i++) {
            const int lr = iclamp(r0 - 2 + i, 0, HH - 1);
            float4 v = *(const float4*)&xin[lr * WW + wl4];
            float4 xp;
            if (sq) { xp.x = v.x*v.x; xp.y = v.y*v.y; xp.z = v.z*v.z; xp.w = v.w*v.w; }
            else    { xp.x = powf(v.x,p); xp.y = powf(v.y,p); xp.z = powf(v.z,p); xp.w = powf(v.w,p); }

            // neighbor edge words (garbage crossings land only on fixed-up cols)
            float Lz = __shfl_up_sync(0xffffffffu,   xp.z, 1);
            float Lw = __shfl_up_sync(0xffffffffu,   xp.w, 1);
            float Rx = __shfl_down_sync(0xffffffffu, xp.x, 1);
            float Ry = __shfl_down_sync(0xffffffffu, xp.y, 1);

            float m = xp.x + xp.y + xp.z;
            float t = xp.w + Rx;
            float4 h;
            h.x = Lz + Lw + m;
            h.y = Lw + m + xp.w;
            h.z = m + t;
            h.w = xp.y + xp.z + t + Ry;

            // sliding vertical 5-sum
            float4& old = hist[i % 5];
            s4.x += h.x - old.x;  s4.y += h.y - old.y;
            s4.z += h.z - old.z;  s4.w += h.w - old.w;
            old = h;

            if (i == NSTEP - 3) { if (ty == BANDS - 1) sft = s4; }   // sf(center 109)

            if (i >= 4) {
                float4 sfv = s4;
                if (i >= NSTEP - 2) { if (ty == BANDS - 1) sfv = sft; }  // rows 110/111
                // horizontal conv-output replication (cols 0,1 <- 2; 110,111 <- 109)
                if (tx == 0)       { sfv.x = sfv.z; sfv.y = sfv.z; }
                if (tx == NCG - 1) { sfv.z = sfv.y; sfv.w = sfv.y; }

                if (act && (i >= 6 || ty != 0)) {
                    const int hrow = r0 + i - 4;
                    // re-load numerator row (L1 hit: loaded 2 steps ago)
                    float4 vv = *(const float4*)&xin[hrow * WW + w4];
                    float4 xq;
                    if (sq) { xq.x=vv.x*vv.x; xq.y=vv.y*vv.y; xq.z=vv.z*vv.z; xq.w=vv.w*vv.w; }
                    else    { xq.x=powf(vv.x,p); xq.y=powf(vv.y,p); xq.z=powf(vv.z,p); xq.w=powf(vv.w,p); }
                    float4 o;
                    o.x = fmaf(wgt * xq.x, frcp(fmaf(sfv.x, k0, sp)), bs);
                    o.y = fmaf(wgt * xq.y, frcp(fmaf(sfv.y, k0, sp)), bs);
                    o.z = fmaf(wgt * xq.z, frcp(fmaf(sfv.z, k0, sp)), bs);
                    o.w = fmaf(wgt * xq.w, frcp(fmaf(sfv.w, k0, sp)), bs);
                    *(float4*)&oimg[hrow * WW + w4] = o;
                }
                // rows 0,1 replicate sf(center 2) = s4 at i==6; reload x (L1 hit)
                if (i == 6) {
                    if (ty == 0 && act) {
                        #pragma unroll
                        for (int rr = 0; rr < 2; rr++) {
                            float4 vv = *(const float4*)&xin[rr * WW + w4];
                            float4 xq;
                            if (sq) { xq.x=vv.x*vv.x; xq.y=vv.y*vv.y; xq.z=vv.z*vv.z; xq.w=vv.w*vv.w; }
                            else    { xq.x=powf(vv.x,p); xq.y=powf(vv.y,p); xq.z=powf(vv.z,p); xq.w=powf(vv.w,p); }
                            float4 o;
                            o.x = fmaf(wgt * xq.x, frcp(fmaf(sfv.x, k0, sp)), bs);
                            o.y = fmaf(wgt * xq.y, frcp(fmaf(sfv.y, k0, sp)), bs);
                            o.z = fmaf(wgt * xq.z, frcp(fmaf(sfv.z, k0, sp)), bs);
                            o.w = fmaf(wgt * xq.w, frcp(fmaf(sfv.w, k0, sp)), bs);
                            *(float4*)&oimg[rr * WW + w4] = o;
                        }
                    }
                }
            }
        }
    } else {
        // ========== GENERAL PATH: direct 25-tap from global (fallback) =====
        if (act) {
            float kc[25];
            #pragma unroll
            for (int q = 0; q < 25; q++) kc[q] = kc_sh[q];
            for (int j = 0; j < BH; j++) {
                const int hrow = r0 + j;
                const int hc = iclamp(hrow, 2, HH - 3);
                float4 o;
                float* op = &o.x;
                #pragma unroll
                for (int jj = 0; jj < 4; jj++) {
                    const int w  = w4 + jj;
                    const int wc = iclamp(w, 2, WW - 3);
                    float acc = 0.0f;
                    #pragma unroll
                    for (int ki = 0; ki < 5; ki++) {
                        const float* row = &xin[(hc + ki - 2) * WW + (wc - 2)];
                        #pragma unroll
                        for (int kj = 0; kj < 5; kj++) {
                            float xv = row[kj];
                            float xpv = sq ? xv * xv : powf(xv, p);
                            acc = fmaf(kc[ki * 5 + kj], xpv, acc);
                        }
                    }
                    float xv = xin[hrow * WW + w];
                    float xpv = sq ? xv * xv : powf(xv, p);
                    op[jj] = wgt * xpv / (sp + acc) + bs;
                }
                *(float4*)&oimg[hrow * WW + w4] = o;
            }
        }
    }
}

extern "C" void kernel_launch(void* const* d_in, const int* in_sizes, int n_in,
                              void* d_out, int out_size)
{
    const float* x          = (const float*)d_in[0];
    const float* sigma      = (const float*)d_in[1];
    const float* pow_p      = (const float*)d_in[2];
    const float* sum_kernel = (const float*)d_in[3];
    const float* weight     = (const float*)d_in[4];
    const float* bias       = (const float*)d_in[5];
    float* out = (float*)d_out;

    dim3 grid(CCH, BBATCH);        // 2048 CTAs, one per (b,c) image
    dim3 block(BX, BANDS, 1);      // 128 threads
    bionorm_kernel<<<grid, block>>>(x, sigma, pow_p, sum_kernel, weight, bias, out);
}

// round 11
// speedup vs baseline: 1.0566x; 1.0566x over previous
#include <cuda_runtime.h>

#define HH 112
#define WW 112
#define CCH 64
#define BBATCH 32
#define BANDS 8
#define BH 14             // output rows per band
#define NSTEP 18          // BH + 4 halo rows
#define BX 32             // lanes; 0..27 own 4-col groups
#define NCG 28
#define NTHREADS 256

typedef unsigned long long u64;

__device__ __forceinline__ float frcp(float d) {
    float r; asm("rcp.approx.f32 %0, %1;" : "=f"(r) : "f"(d)); return r;
}
__device__ __forceinline__ int iclamp(int v, int lo, int hi) {
    return v < lo ? lo : (v > hi ? hi : v);
}
__device__ __forceinline__ u64 pk(float lo, float hi) {
    u64 r; asm("mov.b64 %0, {%1,%2};" : "=l"(r) : "f"(lo), "f"(hi)); return r;
}
__device__ __forceinline__ void upk(u64 v, float& lo, float& hi) {
    asm("mov.b64 {%0,%1}, %2;" : "=f"(lo), "=f"(hi) : "l"(v));
}
__device__ __forceinline__ u64 add2(u64 a, u64 b) {
    u64 r; asm("add.rn.f32x2 %0, %1, %2;" : "=l"(r) : "l"(a), "l"(b)); return r;
}
__device__ __forceinline__ u64 mul2(u64 a, u64 b) {
    u64 r; asm("mul.rn.f32x2 %0, %1, %2;" : "=l"(r) : "l"(a), "l"(b)); return r;
}
__device__ __forceinline__ u64 fma2(u64 a, u64 b, u64 c) {
    u64 r; asm("fma.rn.f32x2 %0, %1, %2, %3;" : "=l"(r) : "l"(a), "l"(b), "l"(c)); return r;
}
// packed xp of a float pair (p==2 fast case or general powf)
__device__ __forceinline__ u64 xp2(float a, float b, bool sq, float p) {
    if (sq) { u64 v = pk(a, b); return mul2(v, v); }
    return pk(powf(a, p), powf(b, p));
}

__global__ __launch_bounds__(NTHREADS, 4)
void bionorm_kernel(const float* __restrict__ x,
                    const float* __restrict__ sigma,
                    const float* __restrict__ pow_p,
                    const float* __restrict__ sum_kernel,
                    const float* __restrict__ weight,
                    const float* __restrict__ bias,
                    float* __restrict__ out)
{
    __shared__ float kc_sh[25];
    __shared__ float sp_sh;
    __shared__ int   uni_sh;

    const int tx  = threadIdx.x;             // lane: column group (0..27 active)
    const int ty  = threadIdx.y;             // band 0..7
    const int tid = ty * BX + tx;
    const int c   = blockIdx.x;
    const int b   = blockIdx.y;
    const int r0  = ty * BH;
    const int w4  = 4 * tx;
    const bool act = (tx < NCG);
    const int wl4 = act ? w4 : WW - 4;       // safe col for idle lanes
    const int wL  = act ? (w4 >= 2 ? w4 - 2 : 0) : WW - 2;   // left halo col (8B aligned)
    const int wR  = act ? (w4 + 4 <= WW - 2 ? w4 + 4 : WW - 2) : WW - 2; // right halo col

    const float p  = pow_p[c];
    const bool  sq = (p == 2.0f);

    if (tid < 25) kc_sh[tid] = sum_kernel[c * 25 + tid];
    if (tid == 0) {
        float s = sigma[c];
        sp_sh = sq ? s * s : powf(s, p);
        const float* kp = sum_kernel + c * 25;
        float k0 = kp[0];
        int u = 1;
        #pragma unroll
        for (int i = 1; i < 25; i++) u &= (kp[i] == k0);
        uni_sh = u;
    }
    __syncthreads();

    const float* __restrict__ xin  = x   + (size_t)(b * CCH + c) * (HH * WW);
    float* __restrict__       oimg = out + (size_t)(b * CCH + c) * (HH * WW);
    const float sp  = sp_sh;
    const float wgt = weight[c];
    const float bs  = bias[c];

    if (uni_sh) {
        // ===== FAST PATH: register-streaming box filter, packed f32x2 =====
        const float k0 = kc_sh[0];
        const u64 K2   = pk(k0, k0);
        const u64 SP2  = pk(sp, sp);
        const u64 WG2  = pk(wgt, wgt);
        const u64 BS2  = pk(bs, bs);
        const u64 NEG1 = pk(-1.0f, -1.0f);

        u64 h01[5], h23[5];                  // hsum history (circular 5)
        u64 s01 = 0, s23 = 0;                // running 5-row sums
        u64 f01 = 0, f23 = 0;                // sf at center 109 (last band)
        #pragma unroll
        for (int q = 0; q < 5; q++) { h01[q] = 0; h23[q] = 0; }

        #pragma unroll
        for (int i = 0; i < NSTEP; i++) {
            const int lr = iclamp(r0 - 2 + i, 0, HH - 1);
            const float* rowp = &xin[lr * WW];
            // three independent loads (all L1-friendly); no shuffles
            float4 v  = *(const float4*)&rowp[wl4];
            float2 vl = *(const float2*)&rowp[wL];
            float2 vr = *(const float2*)&rowp[wR];

            u64 X01 = xp2(v.x, v.y, sq, p);      // (e2,e3)
            u64 X23 = xp2(v.z, v.w, sq, p);      // (e4,e5)
            u64 T0  = xp2(vl.x, vl.y, sq, p);    // (e0,e1)
            u64 T6  = xp2(vr.x, vr.y, sq, p);    // (e6,e7)

            // shifted pairs
            float e0, e1, e2, e3, e4, e5, e6, e7;
            upk(T0, e0, e1); upk(X01, e2, e3); upk(X23, e4, e5); upk(T6, e6, e7);
            u64 T1 = pk(e1, e2);
            u64 T3 = pk(e3, e4);
            u64 T5 = pk(e5, e6);

            // horizontal 5-tap sums (packed): out_j = e_j+..+e_{j+4}
            u64 M   = add2(add2(X01, T3), X23);
            u64 O01 = add2(add2(M, T0), T1);
            u64 O23 = add2(add2(M, T5), T6);

            // sliding vertical 5-sum
            s01 = add2(s01, O01); s01 = fma2(h01[i % 5], NEG1, s01);
            s23 = add2(s23, O23); s23 = fma2(h23[i % 5], NEG1, s23);
            h01[i % 5] = O01; h23[i % 5] = O23;

            if (i == NSTEP - 3) { if (ty == BANDS - 1) { f01 = s01; f23 = s23; } }

            if (i >= 4) {
                u64 sf01 = s01, sf23 = s23;
                if (i >= NSTEP - 2) { if (ty == BANDS - 1) { sf01 = f01; sf23 = f23; } }
                // horizontal conv-output replication (cols 0,1 <- 2; 110,111 <- 109)
                if (tx == 0) {
                    float a, bq; upk(sf23, a, bq); sf01 = pk(a, a);
                }
                if (tx == NCG - 1) {
                    float a, bq; upk(sf01, a, bq); sf23 = pk(bq, bq);
                }

                if (act && (i >= 6 || ty != 0)) {
                    const int hrow = r0 + i - 4;
                    float4 vv = *(const float4*)&xin[hrow * WW + w4];  // L1 hit
                    u64 xq01 = xp2(vv.x, vv.y, sq, p);
                    u64 xq23 = xp2(vv.z, vv.w, sq, p);
                    u64 d01 = fma2(sf01, K2, SP2);
                    u64 d23 = fma2(sf23, K2, SP2);
                    float da, db, dc, dd;
                    upk(d01, da, db); upk(d23, dc, dd);
                    u64 rc01 = pk(frcp(da), frcp(db));
                    u64 rc23 = pk(frcp(dc), frcp(dd));
                    u64 o01 = fma2(mul2(xq01, rc01), WG2, BS2);
                    u64 o23 = fma2(mul2(xq23, rc23), WG2, BS2);
                    float4 o;
                    upk(o01, o.x, o.y); upk(o23, o.z, o.w);
                    *(float4*)&oimg[hrow * WW + w4] = o;
                }
                // rows 0,1 replicate sf(center 2); reload x (L1 hit)
                if (i == 6) {
                    if (ty == 0 && act) {
                        u64 d01 = fma2(sf01, K2, SP2);
                        u64 d23 = fma2(sf23, K2, SP2);
                        float da, db, dc, dd;
                        upk(d01, da, db); upk(d23, dc, dd);
                        u64 rc01 = pk(frcp(da), frcp(db));
                        u64 rc23 = pk(frcp(dc), frcp(dd));
                        #pragma unroll
                        for (int rr = 0; rr < 2; rr++) {
                            float4 vv = *(const float4*)&xin[rr * WW + w4];
                            u64 xq01 = xp2(vv.x, vv.y, sq, p);
                            u64 xq23 = xp2(vv.z, vv.w, sq, p);
                            u64 o01 = fma2(mul2(xq01, rc01), WG2, BS2);
                            u64 o23 = fma2(mul2(xq23, rc23), WG2, BS2);
                            float4 o;
                            upk(o01, o.x, o.y); upk(o23, o.z, o.w);
                            *(float4*)&oimg[rr * WW + w4] = o;
                        }
                    }
                }
            }
        }
    } else {
        // ========== GENERAL PATH: direct 25-tap from global (fallback) =====
        if (act) {
            float kc[25];
            #pragma unroll
            for (int q = 0; q < 25; q++) kc[q] = kc_sh[q];
            for (int j = 0; j < BH; j++) {
                const int hrow = r0 + j;
                const int hc = iclamp(hrow, 2, HH - 3);
                float4 o;
                float* op = &o.x;
                #pragma unroll
                for (int jj = 0; jj < 4; jj++) {
                    const int w  = w4 + jj;
                    const int wc = iclamp(w, 2, WW - 3);
                    float acc = 0.0f;
                    #pragma unroll
                    for (int ki = 0; ki < 5; ki++) {
                        const float* row = &xin[(hc + ki - 2) * WW + (wc - 2)];
                        #pragma unroll
                        for (int kj = 0; kj < 5; kj++) {
                            float xv = row[kj];
                            float xpv = sq ? xv * xv : powf(xv, p);
                            acc = fmaf(kc[ki * 5 + kj], xpv, acc);
                        }
                    }
                    float xv = xin[hrow * WW + w];
                    float xpv = sq ? xv * xv : powf(xv, p);
                    op[jj] = wgt * xpv / (sp + acc) + bs;
                }
                *(float4*)&oimg[hrow * WW + w4] = o;
            }
        }
    }
}

extern "C" void kernel_launch(void* const* d_in, const int* in_sizes, int n_in,
                              void* d_out, int out_size)
{
    const float* x          = (const float*)d_in[0];
    const float* sigma      = (const float*)d_in[1];
    const float* pow_p      = (const float*)d_in[2];
    const float* sum_kernel = (const float*)d_in[3];
    const float* weight     = (const float*)d_in[4];
    const float* bias       = (const float*)d_in[5];
    float* out = (float*)d_out;

    dim3 grid(CCH, BBATCH);        // 2048 CTAs, one per (b,c) image
    dim3 block(BX, BANDS, 1);      // 256 threads
    bionorm_kernel<<<grid, block>>>(x, sigma, pow_p, sum_kernel, weight, bias, out);
}

// round 12
// speedup vs baseline: 1.3105x; 1.2402x over previous
#include <cuda_runtime.h>

#define HH 112
#define WW 112
#define CCH 64
#define BBATCH 32
#define ZSPLIT 2          // CTAs per image (row halves)
#define BANDS 4           // bands per CTA
#define TBANDS 8          // total bands per image
#define BH 14             // output rows per band
#define NSTEP 18          // BH + 4 halo rows
#define BX 32             // lanes; 0..27 own 4-col groups
#define NCG 28
#define NTHREADS 128

__device__ __forceinline__ float frcp(float d) {
    float r; asm("rcp.approx.f32 %0, %1;" : "=f"(r) : "f"(d)); return r;
}
__device__ __forceinline__ int iclamp(int v, int lo, int hi) {
    return v < lo ? lo : (v > hi ? hi : v);
}

__global__ __launch_bounds__(NTHREADS, 6)
void bionorm_kernel(const float* __restrict__ x,
                    const float* __restrict__ sigma,
                    const float* __restrict__ pow_p,
                    const float* __restrict__ sum_kernel,
                    const float* __restrict__ weight,
                    const float* __restrict__ bias,
                    float* __restrict__ out)
{
    __shared__ float kc_sh[25];
    __shared__ float sp_sh;
    __shared__ int   uni_sh;

    const int tx  = threadIdx.x;             // lane: column group (0..27 active)
    const int ty  = threadIdx.y;             // band-in-CTA 0..3
    const int tid = ty * BX + tx;
    const int c   = blockIdx.x;
    const int b   = blockIdx.y;
    const int gband = blockIdx.z * BANDS + ty;   // global band 0..7
    const int r0  = gband * BH;
    const int w4  = 4 * tx;
    const bool act = (tx < NCG);
    const int wl4 = act ? w4 : WW - 4;       // safe col for idle lanes

    const float p  = pow_p[c];
    const bool  sq = (p == 2.0f);

    if (tid < 25) kc_sh[tid] = sum_kernel[c * 25 + tid];
    if (tid == 0) {
        float s = sigma[c];
        sp_sh = sq ? s * s : powf(s, p);
        const float* kp = sum_kernel + c * 25;
        float k0 = kp[0];
        int u = 1;
        #pragma unroll
        for (int i = 1; i < 25; i++) u &= (kp[i] == k0);
        uni_sh = u;
    }
    __syncthreads();

    const float* __restrict__ xin  = x   + (size_t)(b * CCH + c) * (HH * WW);
    float* __restrict__       oimg = out + (size_t)(b * CCH + c) * (HH * WW);
    const float sp  = sp_sh;
    const float wgt = weight[c];
    const float bs  = bias[c];

    if (uni_sh) {
        // ========== FAST PATH: register-streaming separable box filter =====
        const float k0 = kc_sh[0];

        float4 hist[5];                      // hsum history (circular 5)
        float4 xph[3];                       // xp history (lag <= 2)
        float4 s4  = make_float4(0.f, 0.f, 0.f, 0.f);   // running 5-row sum
        float4 sft = make_float4(0.f, 0.f, 0.f, 0.f);   // sf at center 109 (last band)
        #pragma unroll
        for (int q = 0; q < 5; q++) hist[q] = make_float4(0.f, 0.f, 0.f, 0.f);

        #pragma unroll
        for (int i = 0; i < NSTEP; i++) {
            const int lr = iclamp(r0 - 2 + i, 0, HH - 1);
            float4 v = *(const float4*)&xin[lr * WW + wl4];
            float4 xp;
            if (sq) { xp.x = v.x*v.x; xp.y = v.y*v.y; xp.z = v.z*v.z; xp.w = v.w*v.w; }
            else    { xp.x = powf(v.x,p); xp.y = powf(v.y,p); xp.z = powf(v.z,p); xp.w = powf(v.w,p); }

            // neighbor edge words (garbage crossings land only on fixed-up cols)
            float Lz = __shfl_up_sync(0xffffffffu,   xp.z, 1);
            float Lw = __shfl_up_sync(0xffffffffu,   xp.w, 1);
            float Rx = __shfl_down_sync(0xffffffffu, xp.x, 1);
            float Ry = __shfl_down_sync(0xffffffffu, xp.y, 1);

            float m = xp.x + xp.y + xp.z;
            float t = xp.w + Rx;
            float4 h;
            h.x = Lz + Lw + m;
            h.y = Lw + m + xp.w;
            h.z = m + t;
            h.w = xp.y + xp.z + t + Ry;

            // sliding vertical 5-sum
            float4& old = hist[i % 5];
            s4.x += h.x - old.x;  s4.y += h.y - old.y;
            s4.z += h.z - old.z;  s4.w += h.w - old.w;
            old = h;
            xph[i % 3] = xp;

            if (i == NSTEP - 3) { if (gband == TBANDS - 1) sft = s4; }   // sf(center 109)

            if (i >= 4) {
                float4 sfv = s4;
                if (i >= NSTEP - 2) { if (gband == TBANDS - 1) sfv = sft; }  // rows 110/111
                // horizontal conv-output replication (cols 0,1 <- 2; 110,111 <- 109)
                if (tx == 0)       { sfv.x = sfv.z; sfv.y = sfv.z; }
                if (tx == NCG - 1) { sfv.z = sfv.y; sfv.w = sfv.y; }

                const float4 xpv = xph[(i - 2) % 3];
                if (act && (i >= 6 || gband != 0)) {
                    const int hrow = r0 + i - 4;
                    float4 o;
                    o.x = fmaf(wgt * xpv.x, frcp(fmaf(sfv.x, k0, sp)), bs);
                    o.y = fmaf(wgt * xpv.y, frcp(fmaf(sfv.y, k0, sp)), bs);
                    o.z = fmaf(wgt * xpv.z, frcp(fmaf(sfv.z, k0, sp)), bs);
                    o.w = fmaf(wgt * xpv.w, frcp(fmaf(sfv.w, k0, sp)), bs);
                    *(float4*)&oimg[hrow * WW + w4] = o;
                }
                // rows 0,1 replicate sf(center 2) = s4 at i==6; reload x (L1 hit)
                if (i == 6) {
                    if (gband == 0 && act) {
                        #pragma unroll
                        for (int rr = 0; rr < 2; rr++) {
                            float4 vv = *(const float4*)&xin[rr * WW + w4];
                            float4 xq;
                            if (sq) { xq.x=vv.x*vv.x; xq.y=vv.y*vv.y; xq.z=vv.z*vv.z; xq.w=vv.w*vv.w; }
                            else    { xq.x=powf(vv.x,p); xq.y=powf(vv.y,p); xq.z=powf(vv.z,p); xq.w=powf(vv.w,p); }
                            float4 o;
                            o.x = fmaf(wgt * xq.x, frcp(fmaf(sfv.x, k0, sp)), bs);
                            o.y = fmaf(wgt * xq.y, frcp(fmaf(sfv.y, k0, sp)), bs);
                            o.z = fmaf(wgt * xq.z, frcp(fmaf(sfv.z, k0, sp)), bs);
                            o.w = fmaf(wgt * xq.w, frcp(fmaf(sfv.w, k0, sp)), bs);
                            *(float4*)&oimg[rr * WW + w4] = o;
                        }
                    }
                }
            }
        }
    } else {
        // ========== GENERAL PATH: direct 25-tap from global (fallback) =====
        if (act) {
            float kc[25];
            #pragma unroll
            for (int q = 0; q < 25; q++) kc[q] = kc_sh[q];
            for (int j = 0; j < BH; j++) {
                const int hrow = r0 + j;
                const int hc = iclamp(hrow, 2, HH - 3);
                float4 o;
                float* op = &o.x;
                #pragma unroll
                for (int jj = 0; jj < 4; jj++) {
                    const int w  = w4 + jj;
                    const int wc = iclamp(w, 2, WW - 3);
                    float acc = 0.0f;
                    #pragma unroll
                    for (int ki = 0; ki < 5; ki++) {
                        const float* row = &xin[(hc + ki - 2) * WW + (wc - 2)];
                        #pragma unroll
                        for (int kj = 0; kj < 5; kj++) {
                            float xv = row[kj];
                            float xpv = sq ? xv * xv : powf(xv, p);
                            acc = fmaf(kc[ki * 5 + kj], xpv, acc);
                        }
                    }
                    float xv = xin[hrow * WW + w];
                    float xpv = sq ? xv * xv : powf(xv, p);
                    op[jj] = wgt * xpv / (sp + acc) + bs;
                }
                *(float4*)&oimg[hrow * WW + w4] = o;
            }
        }
    }
}

extern "C" void kernel_launch(void* const* d_in, const int* in_sizes, int n_in,
                              void* d_out, int out_size)
{
    const float* x          = (const float*)d_in[0];
    const float* sigma      = (const float*)d_in[1];
    const float* pow_p      = (const float*)d_in[2];
    const float* sum_kernel = (const float*)d_in[3];
    const float* weight     = (const float*)d_in[4];
    const float* bias       = (const float*)d_in[5];
    float* out = (float*)d_out;

    dim3 grid(CCH, BBATCH, ZSPLIT);   // 4096 CTAs
    dim3 block(BX, BANDS, 1);         // 128 threads
    bionorm_kernel<<<grid, block>>>(x, sigma, pow_p, sum_kernel, weight, bias, out);
}